// round 12
// baseline (speedup 1.0000x reference)
#include <cuda_runtime.h>
#include <math.h>

// Problem constants
#define Bv   4
#define Sv   2048
#define DMv  1024
#define NHv  16
#define DKv  64
#define RKv  256
#define MR   (Bv*Sv)      // 8192 rows
#define BHv  (Bv*NHv)     // 64 batch*head

// ---------------- scratch (static device globals; no allocation) -------------
__device__ float g_Tq[MR*RKv];
__device__ float g_Tk[MR*RKv];
__device__ float g_Tv[MR*RKv];
__device__ float g_QH[(size_t)MR*DMv];
__device__ float g_KH[(size_t)MR*DMv];
__device__ float g_VH[(size_t)MR*DMv];
__device__ float g_CTX[(size_t)MR*DMv];
__device__ float g_T4[MR*RKv];
__device__ float g_Y[(size_t)MR*DMv];
__device__ float g_m[BHv*Sv];
__device__ float g_l[BHv*Sv];

// ---------------- fp32 SGEMM body: C(MxN)=A(MxK)@B(KxN) row-major -----------
// 128x128 block tile, BK=16, 256 threads, 8x8 per thread.
__device__ __forceinline__ void sgemm_body(
    const float* __restrict__ A, const float* __restrict__ B,
    float* __restrict__ C, int M, int N, int K)
{
    __shared__ float As[16][128];
    __shared__ float Bs[16][132];

    const int tid  = threadIdx.x;
    const int row0 = blockIdx.y * 128;
    const int col0 = blockIdx.x * 128;
    const int ty = tid >> 4, tx = tid & 15;

    float acc[8][8];
#pragma unroll
    for (int i = 0; i < 8; i++)
#pragma unroll
        for (int j = 0; j < 8; j++) acc[i][j] = 0.f;

    const int a_r0 = tid >> 2;
    const int a_k0 = (tid & 3) * 4;
    const int a_r1 = (tid + 256) >> 2;
    const int b_r0 = tid >> 5;
    const int b_c0 = (tid & 31) * 4;
    const int b_r1 = b_r0 + 8;

    for (int k0 = 0; k0 < K; k0 += 16) {
        float4 a0 = *(const float4*)(A + (size_t)(row0 + a_r0) * K + k0 + a_k0);
        float4 a1 = *(const float4*)(A + (size_t)(row0 + a_r1) * K + k0 + a_k0);
        float4 b0 = *(const float4*)(B + (size_t)(k0 + b_r0) * N + col0 + b_c0);
        float4 b1 = *(const float4*)(B + (size_t)(k0 + b_r1) * N + col0 + b_c0);

        As[a_k0 + 0][a_r0] = a0.x; As[a_k0 + 1][a_r0] = a0.y;
        As[a_k0 + 2][a_r0] = a0.z; As[a_k0 + 3][a_r0] = a0.w;
        As[a_k0 + 0][a_r1] = a1.x; As[a_k0 + 1][a_r1] = a1.y;
        As[a_k0 + 2][a_r1] = a1.z; As[a_k0 + 3][a_r1] = a1.w;
        *(float4*)&Bs[b_r0][b_c0] = b0;
        *(float4*)&Bs[b_r1][b_c0] = b1;
        __syncthreads();

#pragma unroll
        for (int k = 0; k < 16; k++) {
            float ar[8], br[8];
            *(float4*)(ar)     = *(float4*)&As[k][ty * 8];
            *(float4*)(ar + 4) = *(float4*)&As[k][ty * 8 + 4];
            *(float4*)(br)     = *(float4*)&Bs[k][tx * 8];
            *(float4*)(br + 4) = *(float4*)&Bs[k][tx * 8 + 4];
#pragma unroll
            for (int i = 0; i < 8; i++)
#pragma unroll
                for (int j = 0; j < 8; j++)
                    acc[i][j] = fmaf(ar[i], br[j], acc[i][j]);
        }
        __syncthreads();
    }

#pragma unroll
    for (int i = 0; i < 8; i++) {
        float4 c0 = make_float4(acc[i][0], acc[i][1], acc[i][2], acc[i][3]);
        float4 c1 = make_float4(acc[i][4], acc[i][5], acc[i][6], acc[i][7]);
        float* Cp = C + (size_t)(row0 + ty * 8 + i) * N + col0 + tx * 8;
        *(float4*)(Cp)     = c0;
        *(float4*)(Cp + 4) = c1;
    }
}

// batched-3 wrapper: blockIdx.z selects (A,B,C) triple
__global__ __launch_bounds__(256) void sgemm128_b3(
    const float* __restrict__ A0, const float* __restrict__ B0, float* __restrict__ C0,
    const float* __restrict__ A1, const float* __restrict__ B1, float* __restrict__ C1,
    const float* __restrict__ A2, const float* __restrict__ B2, float* __restrict__ C2,
    int M, int N, int K)
{
    int z = blockIdx.z;
    const float* A = (z == 0) ? A0 : (z == 1) ? A1 : A2;
    const float* B = (z == 0) ? B0 : (z == 1) ? B1 : B2;
    float*       C = (z == 0) ? C0 : (z == 1) ? C1 : C2;
    sgemm_body(A, B, C, M, N, K);
}

// ---------------- tf32 mma helpers -------------------------------------------
__device__ __forceinline__ unsigned f2tf(float x) {
    unsigned r;
    asm("cvt.rna.tf32.f32 %0, %1;" : "=r"(r) : "f"(x));
    return r;
}
__device__ __forceinline__ void mma_tf32(float* d, const unsigned* a, const unsigned* b) {
    asm volatile(
        "mma.sync.aligned.m16n8k8.row.col.f32.tf32.tf32.f32 "
        "{%0,%1,%2,%3},{%4,%5,%6,%7},{%8,%9},{%0,%1,%2,%3};"
        : "+f"(d[0]), "+f"(d[1]), "+f"(d[2]), "+f"(d[3])
        : "r"(a[0]), "r"(a[1]), "r"(a[2]), "r"(a[3]), "r"(b[0]), "r"(b[1]));
}

// ---------------- flash attention (tf32 tensor cores) ------------------------
// grid (Sv/64, BHv), 128 threads = 4 warps. Warp w owns S rows w*16..w*16+15.
// mma m16n8k8: QK^T (B = K transposed-read), then PV. Raw scaled scores go to
// attn (normalized later by attn_norm), ctx accumulated online-softmax style.
#define PD 68
#define FLASH_SMEM (4 * 64 * PD * 4)

__global__ __launch_bounds__(128) void flash_tc(
    const float* __restrict__ QH, const float* __restrict__ KH,
    const float* __restrict__ VH, float* __restrict__ attn,
    float* __restrict__ CTX, float* __restrict__ gm, float* __restrict__ gl,
    int write_attn)
{
    extern __shared__ float smf[];
    float* Qs = smf;              // [64][PD] tf32 bits
    float* Ks = Qs + 64 * PD;     // [64][PD] tf32 bits
    float* Vs = Ks + 64 * PD;     // [64][PD] tf32 bits
    float* Ps = Vs + 64 * PD;     // [64][PD] tf32 bits (P values)

    const int qt = blockIdx.x, bh = blockIdx.y;
    const int b = bh >> 4, h = bh & 15;
    const int tid = threadIdx.x;
    const int w = tid >> 5, lane = tid & 31;
    const int qr = lane >> 2;     // groupID 0..7
    const int qc = lane & 3;      // threadInGroup 0..3
    const int rw = w * 16;        // warp row base within 64-row tile

    const size_t head_off = (size_t)b * Sv * DMv + (size_t)h * DKv;
    const float* Qp = QH + head_off;
    const float* Kp = KH + head_off;
    const float* Vp = VH + head_off;

    // load Q tile, scale 1/8, convert tf32
#pragma unroll
    for (int i = 0; i < 8; i++) {
        int idx = tid + i * 128;
        int r = idx >> 4, c4 = (idx & 15) << 2;
        float4 v = *(const float4*)(Qp + (size_t)(qt * 64 + r) * DMv + c4);
        Qs[r * PD + c4 + 0] = __uint_as_float(f2tf(v.x * 0.125f));
        Qs[r * PD + c4 + 1] = __uint_as_float(f2tf(v.y * 0.125f));
        Qs[r * PD + c4 + 2] = __uint_as_float(f2tf(v.z * 0.125f));
        Qs[r * PD + c4 + 3] = __uint_as_float(f2tf(v.w * 0.125f));
    }

    float m0 = -1e30f, m1 = -1e30f, l0 = 0.f, l1 = 0.f;
    float o[8][4];
#pragma unroll
    for (int n = 0; n < 8; n++)
#pragma unroll
        for (int j = 0; j < 4; j++) o[n][j] = 0.f;

    for (int kt = 0; kt < Sv / 64; kt++) {
        __syncthreads();   // previous iteration done with Ks/Vs
        // load K,V tiles (tf32)
#pragma unroll
        for (int i = 0; i < 8; i++) {
            int idx = tid + i * 128;
            int r = idx >> 4, c4 = (idx & 15) << 2;
            float4 v = *(const float4*)(Kp + (size_t)(kt * 64 + r) * DMv + c4);
            Ks[r * PD + c4 + 0] = __uint_as_float(f2tf(v.x));
            Ks[r * PD + c4 + 1] = __uint_as_float(f2tf(v.y));
            Ks[r * PD + c4 + 2] = __uint_as_float(f2tf(v.z));
            Ks[r * PD + c4 + 3] = __uint_as_float(f2tf(v.w));
            float4 u = *(const float4*)(Vp + (size_t)(kt * 64 + r) * DMv + c4);
            Vs[r * PD + c4 + 0] = __uint_as_float(f2tf(u.x));
            Vs[r * PD + c4 + 1] = __uint_as_float(f2tf(u.y));
            Vs[r * PD + c4 + 2] = __uint_as_float(f2tf(u.z));
            Vs[r * PD + c4 + 3] = __uint_as_float(f2tf(u.w));
        }
        __syncthreads();

        // ---- S = Qs @ Ks^T  (per warp: 16 rows x 64 cols) ----
        float s[8][4];
#pragma unroll
        for (int n = 0; n < 8; n++)
#pragma unroll
            for (int j = 0; j < 4; j++) s[n][j] = 0.f;

#pragma unroll
        for (int k0 = 0; k0 < 8; k0++) {
            unsigned a[4];
            int arow = rw + qr, acol = k0 * 8 + qc;
            a[0] = __float_as_uint(Qs[arow * PD + acol]);
            a[1] = __float_as_uint(Qs[(arow + 8) * PD + acol]);
            a[2] = __float_as_uint(Qs[arow * PD + acol + 4]);
            a[3] = __float_as_uint(Qs[(arow + 8) * PD + acol + 4]);
#pragma unroll
            for (int n = 0; n < 8; n++) {
                unsigned bf[2];
                int krow = n * 8 + qr;
                bf[0] = __float_as_uint(Ks[krow * PD + k0 * 8 + qc]);
                bf[1] = __float_as_uint(Ks[krow * PD + k0 * 8 + qc + 4]);
                mma_tf32(s[n], a, bf);
            }
        }

        // ---- write raw scaled scores to attn (normalized later) ----
        if (write_attn) {
            size_t rbase = ((size_t)bh * Sv + qt * 64 + rw + qr) * Sv + kt * 64;
#pragma unroll
            for (int n = 0; n < 8; n++) {
                int col = n * 8 + 2 * qc;
                *(float2*)&attn[rbase + col] = make_float2(s[n][0], s[n][1]);
                *(float2*)&attn[rbase + 8 * (size_t)Sv + col] = make_float2(s[n][2], s[n][3]);
            }
        }

        // ---- online softmax (rows rw+qr and rw+qr+8, quad-reduced) ----
        float mx0 = m0, mx1 = m1;
#pragma unroll
        for (int n = 0; n < 8; n++) {
            mx0 = fmaxf(mx0, fmaxf(s[n][0], s[n][1]));
            mx1 = fmaxf(mx1, fmaxf(s[n][2], s[n][3]));
        }
        mx0 = fmaxf(mx0, __shfl_xor_sync(0xffffffffu, mx0, 1));
        mx0 = fmaxf(mx0, __shfl_xor_sync(0xffffffffu, mx0, 2));
        mx1 = fmaxf(mx1, __shfl_xor_sync(0xffffffffu, mx1, 1));
        mx1 = fmaxf(mx1, __shfl_xor_sync(0xffffffffu, mx1, 2));
        float c0 = __expf(m0 - mx0);
        float c1 = __expf(m1 - mx1);
        m0 = mx0; m1 = mx1;

        float s0 = 0.f, s1 = 0.f;
        const int prow = rw + qr;
#pragma unroll
        for (int n = 0; n < 8; n++) {
            float p00 = __expf(s[n][0] - mx0);
            float p01 = __expf(s[n][1] - mx0);
            float p10 = __expf(s[n][2] - mx1);
            float p11 = __expf(s[n][3] - mx1);
            s0 += p00 + p01;
            s1 += p10 + p11;
            int pcol = n * 8 + 2 * qc;
            Ps[prow * PD + pcol]           = __uint_as_float(f2tf(p00));
            Ps[prow * PD + pcol + 1]       = __uint_as_float(f2tf(p01));
            Ps[(prow + 8) * PD + pcol]     = __uint_as_float(f2tf(p10));
            Ps[(prow + 8) * PD + pcol + 1] = __uint_as_float(f2tf(p11));
        }
        s0 += __shfl_xor_sync(0xffffffffu, s0, 1);
        s0 += __shfl_xor_sync(0xffffffffu, s0, 2);
        s1 += __shfl_xor_sync(0xffffffffu, s1, 1);
        s1 += __shfl_xor_sync(0xffffffffu, s1, 2);
        l0 = l0 * c0 + s0;
        l1 = l1 * c1 + s1;

#pragma unroll
        for (int n = 0; n < 8; n++) {
            o[n][0] *= c0; o[n][1] *= c0;
            o[n][2] *= c1; o[n][3] *= c1;
        }
        __syncwarp();

        // ---- O += P @ V ----
#pragma unroll
        for (int k0 = 0; k0 < 8; k0++) {
            unsigned a[4];
            int arow = rw + qr, acol = k0 * 8 + qc;
            a[0] = __float_as_uint(Ps[arow * PD + acol]);
            a[1] = __float_as_uint(Ps[(arow + 8) * PD + acol]);
            a[2] = __float_as_uint(Ps[arow * PD + acol + 4]);
            a[3] = __float_as_uint(Ps[(arow + 8) * PD + acol + 4]);
#pragma unroll
            for (int n = 0; n < 8; n++) {
                unsigned bf[2];
                bf[0] = __float_as_uint(Vs[(k0 * 8 + qc) * PD + n * 8 + qr]);
                bf[1] = __float_as_uint(Vs[(k0 * 8 + qc + 4) * PD + n * 8 + qr]);
                mma_tf32(o[n], a, bf);
            }
        }
    }

    // epilogue: normalize ctx, write out
    float inv0 = 1.f / l0, inv1 = 1.f / l1;
    size_t crow0 = ((size_t)b * Sv + qt * 64 + rw + qr) * DMv + h * 64;
#pragma unroll
    for (int n = 0; n < 8; n++) {
        int col = n * 8 + 2 * qc;
        *(float2*)&CTX[crow0 + col] =
            make_float2(o[n][0] * inv0, o[n][1] * inv0);
        *(float2*)&CTX[crow0 + 8 * (size_t)DMv + col] =
            make_float2(o[n][2] * inv1, o[n][3] * inv1);
    }
    if (qc == 0) {
        size_t sbase = (size_t)bh * Sv + qt * 64 + rw + qr;
        gm[sbase] = m0;     gl[sbase] = l0;
        gm[sbase + 8] = m1; gl[sbase + 8] = l1;
    }
}

// ---------------- attn normalize: attn = exp(raw - m) / l --------------------
__global__ __launch_bounds__(256) void attn_norm(
    float* __restrict__ attn, const float* __restrict__ gm,
    const float* __restrict__ gl)
{
    size_t i = (size_t)blockIdx.x * blockDim.x + threadIdx.x;   // float4 index
    size_t row = i >> 9;          // 2048 floats = 512 float4 per row
    float m = gm[row];
    float inv = 1.f / gl[row];
    float4 v = ((float4*)attn)[i];
    v.x = __expf(v.x - m) * inv;
    v.y = __expf(v.y - m) * inv;
    v.z = __expf(v.z - m) * inv;
    v.w = __expf(v.w - m) * inv;
    ((float4*)attn)[i] = v;
}

// ---------------- residual add + LayerNorm -----------------------------------
__global__ __launch_bounds__(256) void resid_ln(
    const float* __restrict__ Y, const float* __restrict__ R,
    const float* __restrict__ gamma, const float* __restrict__ beta,
    float* __restrict__ out)
{
    __shared__ float ssum[8], ssq[8], sstat[2];
    const int row = blockIdx.x;
    const int tid = threadIdx.x;
    const int lane = tid & 31, wid = tid >> 5;

    float4 v = *(const float4*)(Y + (size_t)row * DMv + tid * 4);
    float4 r = *(const float4*)(R + (size_t)row * DMv + tid * 4);
    v.x += r.x; v.y += r.y; v.z += r.z; v.w += r.w;

    float s  = v.x + v.y + v.z + v.w;
    float sq = v.x * v.x + v.y * v.y + v.z * v.z + v.w * v.w;
#pragma unroll
    for (int o = 16; o > 0; o >>= 1) {
        s  += __shfl_xor_sync(0xffffffffu, s, o);
        sq += __shfl_xor_sync(0xffffffffu, sq, o);
    }
    if (lane == 0) { ssum[wid] = s; ssq[wid] = sq; }
    __syncthreads();
    if (tid == 0) {
        float ts = 0.f, tq = 0.f;
#pragma unroll
        for (int i = 0; i < 8; i++) { ts += ssum[i]; tq += ssq[i]; }
        float mu = ts * (1.f / DMv);
        float var = tq * (1.f / DMv) - mu * mu;
        sstat[0] = mu;
        sstat[1] = rsqrtf(var + 1e-6f);
    }
    __syncthreads();
    float mu = sstat[0], rstd = sstat[1];

    float4 g = *(const float4*)(gamma + tid * 4);
    float4 be = *(const float4*)(beta + tid * 4);
    float4 o;
    o.x = (v.x - mu) * rstd * g.x + be.x;
    o.y = (v.y - mu) * rstd * g.y + be.y;
    o.z = (v.z - mu) * rstd * g.z + be.z;
    o.w = (v.w - mu) * rstd * g.w + be.w;
    *(float4*)(out + (size_t)row * DMv + tid * 4) = o;
}

// ---------------- launch ------------------------------------------------------
extern "C" void kernel_launch(void* const* d_in, const int* in_sizes, int n_in,
                              void* d_out, int out_size)
{
    const float* q      = (const float*)d_in[0];
    const float* k      = (const float*)d_in[1];
    const float* v      = (const float*)d_in[2];
    const float* w_qs_u = (const float*)d_in[3];
    const float* w_qs_v = (const float*)d_in[4];
    const float* w_ks_u = (const float*)d_in[5];
    const float* w_ks_v = (const float*)d_in[6];
    const float* w_vs_u = (const float*)d_in[7];
    const float* w_vs_v = (const float*)d_in[8];
    const float* fc_u   = (const float*)d_in[9];
    const float* fc_v   = (const float*)d_in[10];
    const float* ln_g   = (const float*)d_in[11];
    const float* ln_b   = (const float*)d_in[12];
    float* out = (float*)d_out;

    float *Tq, *Tk, *Tv, *QHp, *KHp, *VHp, *CTXp, *T4p, *Yp, *mp, *lp;
    cudaGetSymbolAddress((void**)&Tq,  g_Tq);
    cudaGetSymbolAddress((void**)&Tk,  g_Tk);
    cudaGetSymbolAddress((void**)&Tv,  g_Tv);
    cudaGetSymbolAddress((void**)&QHp, g_QH);
    cudaGetSymbolAddress((void**)&KHp, g_KH);
    cudaGetSymbolAddress((void**)&VHp, g_VH);
    cudaGetSymbolAddress((void**)&CTXp, g_CTX);
    cudaGetSymbolAddress((void**)&T4p, g_T4);
    cudaGetSymbolAddress((void**)&Yp,  g_Y);
    cudaGetSymbolAddress((void**)&mp,  g_m);
    cudaGetSymbolAddress((void**)&lp,  g_l);

    const size_t OUTM = (size_t)MR * DMv;                 // 8388608
    const size_t ATTN = (size_t)BHv * Sv * Sv;            // 268435456
    float* attn_ptr = nullptr;
    int wa = 0;
    if ((size_t)out_size >= OUTM + ATTN) { attn_ptr = out + OUTM; wa = 1; }

    cudaFuncSetAttribute(flash_tc,
                         cudaFuncAttributeMaxDynamicSharedMemorySize, FLASH_SMEM);

    dim3 blk(256);
    // low-rank U projections (K=1024 -> N=256), batched into one launch
    sgemm128_b3<<<dim3(RKv / 128, MR / 128, 3), blk>>>(
        q, w_qs_u, Tq,  k, w_ks_u, Tk,  v, w_vs_u, Tv, MR, RKv, DMv);
    // V projections (K=256 -> N=1024), batched
    sgemm128_b3<<<dim3(DMv / 128, MR / 128, 3), blk>>>(
        Tq, w_qs_v, QHp,  Tk, w_ks_v, KHp,  Tv, w_vs_v, VHp, MR, DMv, RKv);
    // attention (tf32 tensor cores)
    flash_tc<<<dim3(Sv / 64, BHv), dim3(128), FLASH_SMEM>>>(
        QHp, KHp, VHp, attn_ptr, CTXp, mp, lp, wa);
    if (wa)
        attn_norm<<<(unsigned)(ATTN / 4 / 256), 256>>>(attn_ptr, mp, lp);
    // FC
    sgemm128_b3<<<dim3(RKv / 128, MR / 128, 1), blk>>>(
        CTXp, fc_u, T4p, CTXp, fc_u, T4p, CTXp, fc_u, T4p, MR, RKv, DMv);
    sgemm128_b3<<<dim3(DMv / 128, MR / 128, 1), blk>>>(
        T4p, fc_v, Yp, T4p, fc_v, Yp, T4p, fc_v, Yp, MR, DMv, RKv);
    // residual + layernorm
    resid_ln<<<MR, blk>>>(Yp, q, ln_g, ln_b, out);
}

// round 13
// speedup vs baseline: 1.0006x; 1.0006x over previous
#include <cuda_runtime.h>
#include <math.h>

// Problem constants
#define Bv   4
#define Sv   2048
#define DMv  1024
#define NHv  16
#define DKv  64
#define RKv  256
#define MR   (Bv*Sv)      // 8192 rows
#define BHv  (Bv*NHv)     // 64 batch*head

// ---------------- scratch (static device globals; no allocation) -------------
__device__ float g_Tq[MR*RKv];
__device__ float g_Tk[MR*RKv];
__device__ float g_Tv[MR*RKv];
__device__ float g_QH[(size_t)MR*DMv];
__device__ float g_KH[(size_t)MR*DMv];
__device__ float g_VH[(size_t)MR*DMv];
__device__ float g_CTX[(size_t)MR*DMv];
__device__ float g_T4[MR*RKv];
__device__ float g_Y[(size_t)MR*DMv];
__device__ float g_m[BHv*Sv];
__device__ float g_l[BHv*Sv];

// ---------------- fp32 SGEMM body: C(MxN)=A(MxK)@B(KxN) row-major -----------
// 128x128 block tile, BK=16, 256 threads, 8x8 per thread.
__device__ __forceinline__ void sgemm_body(
    const float* __restrict__ A, const float* __restrict__ B,
    float* __restrict__ C, int M, int N, int K)
{
    __shared__ float As[16][128];
    __shared__ float Bs[16][132];

    const int tid  = threadIdx.x;
    const int row0 = blockIdx.y * 128;
    const int col0 = blockIdx.x * 128;
    const int ty = tid >> 4, tx = tid & 15;

    float acc[8][8];
#pragma unroll
    for (int i = 0; i < 8; i++)
#pragma unroll
        for (int j = 0; j < 8; j++) acc[i][j] = 0.f;

    const int a_r0 = tid >> 2;
    const int a_k0 = (tid & 3) * 4;
    const int a_r1 = (tid + 256) >> 2;
    const int b_r0 = tid >> 5;
    const int b_c0 = (tid & 31) * 4;
    const int b_r1 = b_r0 + 8;

    for (int k0 = 0; k0 < K; k0 += 16) {
        float4 a0 = *(const float4*)(A + (size_t)(row0 + a_r0) * K + k0 + a_k0);
        float4 a1 = *(const float4*)(A + (size_t)(row0 + a_r1) * K + k0 + a_k0);
        float4 b0 = *(const float4*)(B + (size_t)(k0 + b_r0) * N + col0 + b_c0);
        float4 b1 = *(const float4*)(B + (size_t)(k0 + b_r1) * N + col0 + b_c0);

        As[a_k0 + 0][a_r0] = a0.x; As[a_k0 + 1][a_r0] = a0.y;
        As[a_k0 + 2][a_r0] = a0.z; As[a_k0 + 3][a_r0] = a0.w;
        As[a_k0 + 0][a_r1] = a1.x; As[a_k0 + 1][a_r1] = a1.y;
        As[a_k0 + 2][a_r1] = a1.z; As[a_k0 + 3][a_r1] = a1.w;
        *(float4*)&Bs[b_r0][b_c0] = b0;
        *(float4*)&Bs[b_r1][b_c0] = b1;
        __syncthreads();

#pragma unroll
        for (int k = 0; k < 16; k++) {
            float ar[8], br[8];
            *(float4*)(ar)     = *(float4*)&As[k][ty * 8];
            *(float4*)(ar + 4) = *(float4*)&As[k][ty * 8 + 4];
            *(float4*)(br)     = *(float4*)&Bs[k][tx * 8];
            *(float4*)(br + 4) = *(float4*)&Bs[k][tx * 8 + 4];
#pragma unroll
            for (int i = 0; i < 8; i++)
#pragma unroll
                for (int j = 0; j < 8; j++)
                    acc[i][j] = fmaf(ar[i], br[j], acc[i][j]);
        }
        __syncthreads();
    }

#pragma unroll
    for (int i = 0; i < 8; i++) {
        float4 c0 = make_float4(acc[i][0], acc[i][1], acc[i][2], acc[i][3]);
        float4 c1 = make_float4(acc[i][4], acc[i][5], acc[i][6], acc[i][7]);
        float* Cp = C + (size_t)(row0 + ty * 8 + i) * N + col0 + tx * 8;
        *(float4*)(Cp)     = c0;
        *(float4*)(Cp + 4) = c1;
    }
}

// batched-3 wrapper: blockIdx.z selects (A,B,C) triple
__global__ __launch_bounds__(256) void sgemm128_b3(
    const float* __restrict__ A0, const float* __restrict__ B0, float* __restrict__ C0,
    const float* __restrict__ A1, const float* __restrict__ B1, float* __restrict__ C1,
    const float* __restrict__ A2, const float* __restrict__ B2, float* __restrict__ C2,
    int M, int N, int K)
{
    int z = blockIdx.z;
    const float* A = (z == 0) ? A0 : (z == 1) ? A1 : A2;
    const float* B = (z == 0) ? B0 : (z == 1) ? B1 : B2;
    float*       C = (z == 0) ? C0 : (z == 1) ? C1 : C2;
    sgemm_body(A, B, C, M, N, K);
}

// ---------------- tf32 mma helpers -------------------------------------------
__device__ __forceinline__ unsigned f2tf(float x) {
    unsigned r;
    asm("cvt.rna.tf32.f32 %0, %1;" : "=r"(r) : "f"(x));
    return r;
}
__device__ __forceinline__ void mma_tf32(float* d, const unsigned* a, const unsigned* b) {
    asm volatile(
        "mma.sync.aligned.m16n8k8.row.col.f32.tf32.tf32.f32 "
        "{%0,%1,%2,%3},{%4,%5,%6,%7},{%8,%9},{%0,%1,%2,%3};"
        : "+f"(d[0]), "+f"(d[1]), "+f"(d[2]), "+f"(d[3])
        : "r"(a[0]), "r"(a[1]), "r"(a[2]), "r"(a[3]), "r"(b[0]), "r"(b[1]));
}

// ---------------- flash attention (tf32 tensor cores) ------------------------
// grid (Sv/64, BHv), 128 threads = 4 warps. Warp w owns S rows w*16..w*16+15.
// mma m16n8k8: QK^T (B = K transposed-read), then PV. Raw scaled scores go to
// attn (normalized later by attn_norm), ctx accumulated online-softmax style.
#define PD 68
#define FLASH_SMEM (4 * 64 * PD * 4)

__global__ __launch_bounds__(128) void flash_tc(
    const float* __restrict__ QH, const float* __restrict__ KH,
    const float* __restrict__ VH, float* __restrict__ attn,
    float* __restrict__ CTX, float* __restrict__ gm, float* __restrict__ gl,
    int write_attn)
{
    extern __shared__ float smf[];
    float* Qs = smf;              // [64][PD] tf32 bits
    float* Ks = Qs + 64 * PD;     // [64][PD] tf32 bits
    float* Vs = Ks + 64 * PD;     // [64][PD] tf32 bits
    float* Ps = Vs + 64 * PD;     // [64][PD] tf32 bits (P values)

    const int qt = blockIdx.x, bh = blockIdx.y;
    const int b = bh >> 4, h = bh & 15;
    const int tid = threadIdx.x;
    const int w = tid >> 5, lane = tid & 31;
    const int qr = lane >> 2;     // groupID 0..7
    const int qc = lane & 3;      // threadInGroup 0..3
    const int rw = w * 16;        // warp row base within 64-row tile

    const size_t head_off = (size_t)b * Sv * DMv + (size_t)h * DKv;
    const float* Qp = QH + head_off;
    const float* Kp = KH + head_off;
    const float* Vp = VH + head_off;

    // load Q tile, scale 1/8, convert tf32
#pragma unroll
    for (int i = 0; i < 8; i++) {
        int idx = tid + i * 128;
        int r = idx >> 4, c4 = (idx & 15) << 2;
        float4 v = *(const float4*)(Qp + (size_t)(qt * 64 + r) * DMv + c4);
        Qs[r * PD + c4 + 0] = __uint_as_float(f2tf(v.x * 0.125f));
        Qs[r * PD + c4 + 1] = __uint_as_float(f2tf(v.y * 0.125f));
        Qs[r * PD + c4 + 2] = __uint_as_float(f2tf(v.z * 0.125f));
        Qs[r * PD + c4 + 3] = __uint_as_float(f2tf(v.w * 0.125f));
    }

    float m0 = -1e30f, m1 = -1e30f, l0 = 0.f, l1 = 0.f;
    float o[8][4];
#pragma unroll
    for (int n = 0; n < 8; n++)
#pragma unroll
        for (int j = 0; j < 4; j++) o[n][j] = 0.f;

    for (int kt = 0; kt < Sv / 64; kt++) {
        __syncthreads();   // previous iteration done with Ks/Vs
        // load K,V tiles (tf32)
#pragma unroll
        for (int i = 0; i < 8; i++) {
            int idx = tid + i * 128;
            int r = idx >> 4, c4 = (idx & 15) << 2;
            float4 v = *(const float4*)(Kp + (size_t)(kt * 64 + r) * DMv + c4);
            Ks[r * PD + c4 + 0] = __uint_as_float(f2tf(v.x));
            Ks[r * PD + c4 + 1] = __uint_as_float(f2tf(v.y));
            Ks[r * PD + c4 + 2] = __uint_as_float(f2tf(v.z));
            Ks[r * PD + c4 + 3] = __uint_as_float(f2tf(v.w));
            float4 u = *(const float4*)(Vp + (size_t)(kt * 64 + r) * DMv + c4);
            Vs[r * PD + c4 + 0] = __uint_as_float(f2tf(u.x));
            Vs[r * PD + c4 + 1] = __uint_as_float(f2tf(u.y));
            Vs[r * PD + c4 + 2] = __uint_as_float(f2tf(u.z));
            Vs[r * PD + c4 + 3] = __uint_as_float(f2tf(u.w));
        }
        __syncthreads();

        // ---- S = Qs @ Ks^T  (per warp: 16 rows x 64 cols) ----
        float s[8][4];
#pragma unroll
        for (int n = 0; n < 8; n++)
#pragma unroll
            for (int j = 0; j < 4; j++) s[n][j] = 0.f;

#pragma unroll
        for (int k0 = 0; k0 < 8; k0++) {
            unsigned a[4];
            int arow = rw + qr, acol = k0 * 8 + qc;
            a[0] = __float_as_uint(Qs[arow * PD + acol]);
            a[1] = __float_as_uint(Qs[(arow + 8) * PD + acol]);
            a[2] = __float_as_uint(Qs[arow * PD + acol + 4]);
            a[3] = __float_as_uint(Qs[(arow + 8) * PD + acol + 4]);
#pragma unroll
            for (int n = 0; n < 8; n++) {
                unsigned bf[2];
                int krow = n * 8 + qr;
                bf[0] = __float_as_uint(Ks[krow * PD + k0 * 8 + qc]);
                bf[1] = __float_as_uint(Ks[krow * PD + k0 * 8 + qc + 4]);
                mma_tf32(s[n], a, bf);
            }
        }

        // ---- write raw scaled scores to attn (normalized later) ----
        if (write_attn) {
            size_t rbase = ((size_t)bh * Sv + qt * 64 + rw + qr) * Sv + kt * 64;
#pragma unroll
            for (int n = 0; n < 8; n++) {
                int col = n * 8 + 2 * qc;
                *(float2*)&attn[rbase + col] = make_float2(s[n][0], s[n][1]);
                *(float2*)&attn[rbase + 8 * (size_t)Sv + col] = make_float2(s[n][2], s[n][3]);
            }
        }

        // ---- online softmax (rows rw+qr and rw+qr+8, quad-reduced) ----
        float mx0 = m0, mx1 = m1;
#pragma unroll
        for (int n = 0; n < 8; n++) {
            mx0 = fmaxf(mx0, fmaxf(s[n][0], s[n][1]));
            mx1 = fmaxf(mx1, fmaxf(s[n][2], s[n][3]));
        }
        mx0 = fmaxf(mx0, __shfl_xor_sync(0xffffffffu, mx0, 1));
        mx0 = fmaxf(mx0, __shfl_xor_sync(0xffffffffu, mx0, 2));
        mx1 = fmaxf(mx1, __shfl_xor_sync(0xffffffffu, mx1, 1));
        mx1 = fmaxf(mx1, __shfl_xor_sync(0xffffffffu, mx1, 2));
        float c0 = __expf(m0 - mx0);
        float c1 = __expf(m1 - mx1);
        m0 = mx0; m1 = mx1;

        float s0 = 0.f, s1 = 0.f;
        const int prow = rw + qr;
#pragma unroll
        for (int n = 0; n < 8; n++) {
            float p00 = __expf(s[n][0] - mx0);
            float p01 = __expf(s[n][1] - mx0);
            float p10 = __expf(s[n][2] - mx1);
            float p11 = __expf(s[n][3] - mx1);
            s0 += p00 + p01;
            s1 += p10 + p11;
            int pcol = n * 8 + 2 * qc;
            Ps[prow * PD + pcol]           = __uint_as_float(f2tf(p00));
            Ps[prow * PD + pcol + 1]       = __uint_as_float(f2tf(p01));
            Ps[(prow + 8) * PD + pcol]     = __uint_as_float(f2tf(p10));
            Ps[(prow + 8) * PD + pcol + 1] = __uint_as_float(f2tf(p11));
        }
        s0 += __shfl_xor_sync(0xffffffffu, s0, 1);
        s0 += __shfl_xor_sync(0xffffffffu, s0, 2);
        s1 += __shfl_xor_sync(0xffffffffu, s1, 1);
        s1 += __shfl_xor_sync(0xffffffffu, s1, 2);
        l0 = l0 * c0 + s0;
        l1 = l1 * c1 + s1;

#pragma unroll
        for (int n = 0; n < 8; n++) {
            o[n][0] *= c0; o[n][1] *= c0;
            o[n][2] *= c1; o[n][3] *= c1;
        }
        __syncwarp();

        // ---- O += P @ V ----
#pragma unroll
        for (int k0 = 0; k0 < 8; k0++) {
            unsigned a[4];
            int arow = rw + qr, acol = k0 * 8 + qc;
            a[0] = __float_as_uint(Ps[arow * PD + acol]);
            a[1] = __float_as_uint(Ps[(arow + 8) * PD + acol]);
            a[2] = __float_as_uint(Ps[arow * PD + acol + 4]);
            a[3] = __float_as_uint(Ps[(arow + 8) * PD + acol + 4]);
#pragma unroll
            for (int n = 0; n < 8; n++) {
                unsigned bf[2];
                bf[0] = __float_as_uint(Vs[(k0 * 8 + qc) * PD + n * 8 + qr]);
                bf[1] = __float_as_uint(Vs[(k0 * 8 + qc + 4) * PD + n * 8 + qr]);
                mma_tf32(o[n], a, bf);
            }
        }
    }

    // epilogue: normalize ctx, write out
    float inv0 = 1.f / l0, inv1 = 1.f / l1;
    size_t crow0 = ((size_t)b * Sv + qt * 64 + rw + qr) * DMv + h * 64;
#pragma unroll
    for (int n = 0; n < 8; n++) {
        int col = n * 8 + 2 * qc;
        *(float2*)&CTX[crow0 + col] =
            make_float2(o[n][0] * inv0, o[n][1] * inv0);
        *(float2*)&CTX[crow0 + 8 * (size_t)DMv + col] =
            make_float2(o[n][2] * inv1, o[n][3] * inv1);
    }
    if (qc == 0) {
        size_t sbase = (size_t)bh * Sv + qt * 64 + rw + qr;
        gm[sbase] = m0;     gl[sbase] = l0;
        gm[sbase + 8] = m1; gl[sbase + 8] = l1;
    }
}

// ---------------- attn normalize: attn = exp(raw - m) / l --------------------
__global__ __launch_bounds__(256) void attn_norm(
    float* __restrict__ attn, const float* __restrict__ gm,
    const float* __restrict__ gl)
{
    size_t i = (size_t)blockIdx.x * blockDim.x + threadIdx.x;   // float4 index
    size_t row = i >> 9;          // 2048 floats = 512 float4 per row
    float m = gm[row];
    float inv = 1.f / gl[row];
    float4 v = ((float4*)attn)[i];
    v.x = __expf(v.x - m) * inv;
    v.y = __expf(v.y - m) * inv;
    v.z = __expf(v.z - m) * inv;
    v.w = __expf(v.w - m) * inv;
    ((float4*)attn)[i] = v;
}

// ---------------- residual add + LayerNorm -----------------------------------
__global__ __launch_bounds__(256) void resid_ln(
    const float* __restrict__ Y, const float* __restrict__ R,
    const float* __restrict__ gamma, const float* __restrict__ beta,
    float* __restrict__ out)
{
    __shared__ float ssum[8], ssq[8], sstat[2];
    const int row = blockIdx.x;
    const int tid = threadIdx.x;
    const int lane = tid & 31, wid = tid >> 5;

    float4 v = *(const float4*)(Y + (size_t)row * DMv + tid * 4);
    float4 r = *(const float4*)(R + (size_t)row * DMv + tid * 4);
    v.x += r.x; v.y += r.y; v.z += r.z; v.w += r.w;

    float s  = v.x + v.y + v.z + v.w;
    float sq = v.x * v.x + v.y * v.y + v.z * v.z + v.w * v.w;
#pragma unroll
    for (int o = 16; o > 0; o >>= 1) {
        s  += __shfl_xor_sync(0xffffffffu, s, o);
        sq += __shfl_xor_sync(0xffffffffu, sq, o);
    }
    if (lane == 0) { ssum[wid] = s; ssq[wid] = sq; }
    __syncthreads();
    if (tid == 0) {
        float ts = 0.f, tq = 0.f;
#pragma unroll
        for (int i = 0; i < 8; i++) { ts += ssum[i]; tq += ssq[i]; }
        float mu = ts * (1.f / DMv);
        float var = tq * (1.f / DMv) - mu * mu;
        sstat[0] = mu;
        sstat[1] = rsqrtf(var + 1e-6f);
    }
    __syncthreads();
    float mu = sstat[0], rstd = sstat[1];

    float4 g = *(const float4*)(gamma + tid * 4);
    float4 be = *(const float4*)(beta + tid * 4);
    float4 o;
    o.x = (v.x - mu) * rstd * g.x + be.x;
    o.y = (v.y - mu) * rstd * g.y + be.y;
    o.z = (v.z - mu) * rstd * g.z + be.z;
    o.w = (v.w - mu) * rstd * g.w + be.w;
    *(float4*)(out + (size_t)row * DMv + tid * 4) = o;
}

// ---------------- launch ------------------------------------------------------
extern "C" void kernel_launch(void* const* d_in, const int* in_sizes, int n_in,
                              void* d_out, int out_size)
{
    const float* q      = (const float*)d_in[0];
    const float* k      = (const float*)d_in[1];
    const float* v      = (const float*)d_in[2];
    const float* w_qs_u = (const float*)d_in[3];
    const float* w_qs_v = (const float*)d_in[4];
    const float* w_ks_u = (const float*)d_in[5];
    const float* w_ks_v = (const float*)d_in[6];
    const float* w_vs_u = (const float*)d_in[7];
    const float* w_vs_v = (const float*)d_in[8];
    const float* fc_u   = (const float*)d_in[9];
    const float* fc_v   = (const float*)d_in[10];
    const float* ln_g   = (const float*)d_in[11];
    const float* ln_b   = (const float*)d_in[12];
    float* out = (float*)d_out;

    float *Tq, *Tk, *Tv, *QHp, *KHp, *VHp, *CTXp, *T4p, *Yp, *mp, *lp;
    cudaGetSymbolAddress((void**)&Tq,  g_Tq);
    cudaGetSymbolAddress((void**)&Tk,  g_Tk);
    cudaGetSymbolAddress((void**)&Tv,  g_Tv);
    cudaGetSymbolAddress((void**)&QHp, g_QH);
    cudaGetSymbolAddress((void**)&KHp, g_KH);
    cudaGetSymbolAddress((void**)&VHp, g_VH);
    cudaGetSymbolAddress((void**)&CTXp, g_CTX);
    cudaGetSymbolAddress((void**)&T4p, g_T4);
    cudaGetSymbolAddress((void**)&Yp,  g_Y);
    cudaGetSymbolAddress((void**)&mp,  g_m);
    cudaGetSymbolAddress((void**)&lp,  g_l);

    const size_t OUTM = (size_t)MR * DMv;                 // 8388608
    const size_t ATTN = (size_t)BHv * Sv * Sv;            // 268435456
    float* attn_ptr = nullptr;
    int wa = 0;
    if ((size_t)out_size >= OUTM + ATTN) { attn_ptr = out + OUTM; wa = 1; }

    cudaFuncSetAttribute(flash_tc,
                         cudaFuncAttributeMaxDynamicSharedMemorySize, FLASH_SMEM);

    dim3 blk(256);
    // low-rank U projections (K=1024 -> N=256), batched into one launch
    sgemm128_b3<<<dim3(RKv / 128, MR / 128, 3), blk>>>(
        q, w_qs_u, Tq,  k, w_ks_u, Tk,  v, w_vs_u, Tv, MR, RKv, DMv);
    // V projections (K=256 -> N=1024), batched
    sgemm128_b3<<<dim3(DMv / 128, MR / 128, 3), blk>>>(
        Tq, w_qs_v, QHp,  Tk, w_ks_v, KHp,  Tv, w_vs_v, VHp, MR, DMv, RKv);
    // attention (tf32 tensor cores)
    flash_tc<<<dim3(Sv / 64, BHv), dim3(128), FLASH_SMEM>>>(
        QHp, KHp, VHp, attn_ptr, CTXp, mp, lp, wa);
    if (wa)
        attn_norm<<<(unsigned)(ATTN / 4 / 256), 256>>>(attn_ptr, mp, lp);
    // FC
    sgemm128_b3<<<dim3(RKv / 128, MR / 128, 1), blk>>>(
        CTXp, fc_u, T4p, CTXp, fc_u, T4p, CTXp, fc_u, T4p, MR, RKv, DMv);
    sgemm128_b3<<<dim3(DMv / 128, MR / 128, 1), blk>>>(
        T4p, fc_v, Yp, T4p, fc_v, Yp, T4p, fc_v, Yp, MR, DMv, RKv);
    // residual + layernorm
    resid_ln<<<MR, blk>>>(Yp, q, ln_g, ln_b, out);
}

// round 14
// speedup vs baseline: 1.0007x; 1.0001x over previous
#include <cuda_runtime.h>
#include <math.h>

// Problem constants
#define Bv   4
#define Sv   2048
#define DMv  1024
#define NHv  16
#define DKv  64
#define RKv  256
#define MR   (Bv*Sv)      // 8192 rows
#define BHv  (Bv*NHv)     // 64 batch*head

// ---------------- scratch (static device globals; no allocation) -------------
__device__ float g_Tq[MR*RKv];
__device__ float g_Tk[MR*RKv];
__device__ float g_Tv[MR*RKv];
__device__ float g_QH[(size_t)MR*DMv];
__device__ float g_KH[(size_t)MR*DMv];
__device__ float g_VH[(size_t)MR*DMv];
__device__ float g_CTX[(size_t)MR*DMv];
__device__ float g_T4[MR*RKv];
__device__ float g_Y[(size_t)MR*DMv];
__device__ float g_m[BHv*Sv];
__device__ float g_l[BHv*Sv];

// ---------------- fp32 SGEMM body: C(MxN)=A(MxK)@B(KxN) row-major -----------
// 128x128 block tile, BK=16, 256 threads, 8x8 per thread.
__device__ __forceinline__ void sgemm_body(
    const float* __restrict__ A, const float* __restrict__ B,
    float* __restrict__ C, int M, int N, int K)
{
    __shared__ float As[16][128];
    __shared__ float Bs[16][132];

    const int tid  = threadIdx.x;
    const int row0 = blockIdx.y * 128;
    const int col0 = blockIdx.x * 128;
    const int ty = tid >> 4, tx = tid & 15;

    float acc[8][8];
#pragma unroll
    for (int i = 0; i < 8; i++)
#pragma unroll
        for (int j = 0; j < 8; j++) acc[i][j] = 0.f;

    const int a_r0 = tid >> 2;
    const int a_k0 = (tid & 3) * 4;
    const int a_r1 = (tid + 256) >> 2;
    const int b_r0 = tid >> 5;
    const int b_c0 = (tid & 31) * 4;
    const int b_r1 = b_r0 + 8;

    for (int k0 = 0; k0 < K; k0 += 16) {
        float4 a0 = *(const float4*)(A + (size_t)(row0 + a_r0) * K + k0 + a_k0);
        float4 a1 = *(const float4*)(A + (size_t)(row0 + a_r1) * K + k0 + a_k0);
        float4 b0 = *(const float4*)(B + (size_t)(k0 + b_r0) * N + col0 + b_c0);
        float4 b1 = *(const float4*)(B + (size_t)(k0 + b_r1) * N + col0 + b_c0);

        As[a_k0 + 0][a_r0] = a0.x; As[a_k0 + 1][a_r0] = a0.y;
        As[a_k0 + 2][a_r0] = a0.z; As[a_k0 + 3][a_r0] = a0.w;
        As[a_k0 + 0][a_r1] = a1.x; As[a_k0 + 1][a_r1] = a1.y;
        As[a_k0 + 2][a_r1] = a1.z; As[a_k0 + 3][a_r1] = a1.w;
        *(float4*)&Bs[b_r0][b_c0] = b0;
        *(float4*)&Bs[b_r1][b_c0] = b1;
        __syncthreads();

#pragma unroll
        for (int k = 0; k < 16; k++) {
            float ar[8], br[8];
            *(float4*)(ar)     = *(float4*)&As[k][ty * 8];
            *(float4*)(ar + 4) = *(float4*)&As[k][ty * 8 + 4];
            *(float4*)(br)     = *(float4*)&Bs[k][tx * 8];
            *(float4*)(br + 4) = *(float4*)&Bs[k][tx * 8 + 4];
#pragma unroll
            for (int i = 0; i < 8; i++)
#pragma unroll
                for (int j = 0; j < 8; j++)
                    acc[i][j] = fmaf(ar[i], br[j], acc[i][j]);
        }
        __syncthreads();
    }

#pragma unroll
    for (int i = 0; i < 8; i++) {
        float4 c0 = make_float4(acc[i][0], acc[i][1], acc[i][2], acc[i][3]);
        float4 c1 = make_float4(acc[i][4], acc[i][5], acc[i][6], acc[i][7]);
        float* Cp = C + (size_t)(row0 + ty * 8 + i) * N + col0 + tx * 8;
        *(float4*)(Cp)     = c0;
        *(float4*)(Cp + 4) = c1;
    }
}

// batched-3 wrapper: blockIdx.z selects (A,B,C) triple
__global__ __launch_bounds__(256) void sgemm128_b3(
    const float* __restrict__ A0, const float* __restrict__ B0, float* __restrict__ C0,
    const float* __restrict__ A1, const float* __restrict__ B1, float* __restrict__ C1,
    const float* __restrict__ A2, const float* __restrict__ B2, float* __restrict__ C2,
    int M, int N, int K)
{
    int z = blockIdx.z;
    const float* A = (z == 0) ? A0 : (z == 1) ? A1 : A2;
    const float* B = (z == 0) ? B0 : (z == 1) ? B1 : B2;
    float*       C = (z == 0) ? C0 : (z == 1) ? C1 : C2;
    sgemm_body(A, B, C, M, N, K);
}

// ---------------- tf32 mma helpers -------------------------------------------
__device__ __forceinline__ unsigned f2tf(float x) {
    unsigned r;
    asm("cvt.rna.tf32.f32 %0, %1;" : "=r"(r) : "f"(x));
    return r;
}
__device__ __forceinline__ void mma_tf32(float* d, const unsigned* a, const unsigned* b) {
    asm volatile(
        "mma.sync.aligned.m16n8k8.row.col.f32.tf32.tf32.f32 "
        "{%0,%1,%2,%3},{%4,%5,%6,%7},{%8,%9},{%0,%1,%2,%3};"
        : "+f"(d[0]), "+f"(d[1]), "+f"(d[2]), "+f"(d[3])
        : "r"(a[0]), "r"(a[1]), "r"(a[2]), "r"(a[3]), "r"(b[0]), "r"(b[1]));
}

// ---------------- flash attention (tf32 tensor cores) ------------------------
// grid (Sv/64, BHv), 128 threads = 4 warps. Warp w owns S rows w*16..w*16+15.
// mma m16n8k8: QK^T (B = K transposed-read), then PV. Raw scaled scores go to
// attn (normalized later by attn_norm), ctx accumulated online-softmax style.
#define PD 68
#define FLASH_SMEM (4 * 64 * PD * 4)

__global__ __launch_bounds__(128) void flash_tc(
    const float* __restrict__ QH, const float* __restrict__ KH,
    const float* __restrict__ VH, float* __restrict__ attn,
    float* __restrict__ CTX, float* __restrict__ gm, float* __restrict__ gl,
    int write_attn)
{
    extern __shared__ float smf[];
    float* Qs = smf;              // [64][PD] tf32 bits
    float* Ks = Qs + 64 * PD;     // [64][PD] tf32 bits
    float* Vs = Ks + 64 * PD;     // [64][PD] tf32 bits
    float* Ps = Vs + 64 * PD;     // [64][PD] tf32 bits (P values)

    const int qt = blockIdx.x, bh = blockIdx.y;
    const int b = bh >> 4, h = bh & 15;
    const int tid = threadIdx.x;
    const int w = tid >> 5, lane = tid & 31;
    const int qr = lane >> 2;     // groupID 0..7
    const int qc = lane & 3;      // threadInGroup 0..3
    const int rw = w * 16;        // warp row base within 64-row tile

    const size_t head_off = (size_t)b * Sv * DMv + (size_t)h * DKv;
    const float* Qp = QH + head_off;
    const float* Kp = KH + head_off;
    const float* Vp = VH + head_off;

    // load Q tile, scale 1/8, convert tf32
#pragma unroll
    for (int i = 0; i < 8; i++) {
        int idx = tid + i * 128;
        int r = idx >> 4, c4 = (idx & 15) << 2;
        float4 v = *(const float4*)(Qp + (size_t)(qt * 64 + r) * DMv + c4);
        Qs[r * PD + c4 + 0] = __uint_as_float(f2tf(v.x * 0.125f));
        Qs[r * PD + c4 + 1] = __uint_as_float(f2tf(v.y * 0.125f));
        Qs[r * PD + c4 + 2] = __uint_as_float(f2tf(v.z * 0.125f));
        Qs[r * PD + c4 + 3] = __uint_as_float(f2tf(v.w * 0.125f));
    }

    float m0 = -1e30f, m1 = -1e30f, l0 = 0.f, l1 = 0.f;
    float o[8][4];
#pragma unroll
    for (int n = 0; n < 8; n++)
#pragma unroll
        for (int j = 0; j < 4; j++) o[n][j] = 0.f;

    for (int kt = 0; kt < Sv / 64; kt++) {
        __syncthreads();   // previous iteration done with Ks/Vs
        // load K,V tiles (tf32)
#pragma unroll
        for (int i = 0; i < 8; i++) {
            int idx = tid + i * 128;
            int r = idx >> 4, c4 = (idx & 15) << 2;
            float4 v = *(const float4*)(Kp + (size_t)(kt * 64 + r) * DMv + c4);
            Ks[r * PD + c4 + 0] = __uint_as_float(f2tf(v.x));
            Ks[r * PD + c4 + 1] = __uint_as_float(f2tf(v.y));
            Ks[r * PD + c4 + 2] = __uint_as_float(f2tf(v.z));
            Ks[r * PD + c4 + 3] = __uint_as_float(f2tf(v.w));
            float4 u = *(const float4*)(Vp + (size_t)(kt * 64 + r) * DMv + c4);
            Vs[r * PD + c4 + 0] = __uint_as_float(f2tf(u.x));
            Vs[r * PD + c4 + 1] = __uint_as_float(f2tf(u.y));
            Vs[r * PD + c4 + 2] = __uint_as_float(f2tf(u.z));
            Vs[r * PD + c4 + 3] = __uint_as_float(f2tf(u.w));
        }
        __syncthreads();

        // ---- S = Qs @ Ks^T  (per warp: 16 rows x 64 cols) ----
        float s[8][4];
#pragma unroll
        for (int n = 0; n < 8; n++)
#pragma unroll
            for (int j = 0; j < 4; j++) s[n][j] = 0.f;

#pragma unroll
        for (int k0 = 0; k0 < 8; k0++) {
            unsigned a[4];
            int arow = rw + qr, acol = k0 * 8 + qc;
            a[0] = __float_as_uint(Qs[arow * PD + acol]);
            a[1] = __float_as_uint(Qs[(arow + 8) * PD + acol]);
            a[2] = __float_as_uint(Qs[arow * PD + acol + 4]);
            a[3] = __float_as_uint(Qs[(arow + 8) * PD + acol + 4]);
#pragma unroll
            for (int n = 0; n < 8; n++) {
                unsigned bf[2];
                int krow = n * 8 + qr;
                bf[0] = __float_as_uint(Ks[krow * PD + k0 * 8 + qc]);
                bf[1] = __float_as_uint(Ks[krow * PD + k0 * 8 + qc + 4]);
                mma_tf32(s[n], a, bf);
            }
        }

        // ---- write raw scaled scores to attn (normalized later) ----
        if (write_attn) {
            size_t rbase = ((size_t)bh * Sv + qt * 64 + rw + qr) * Sv + kt * 64;
#pragma unroll
            for (int n = 0; n < 8; n++) {
                int col = n * 8 + 2 * qc;
                *(float2*)&attn[rbase + col] = make_float2(s[n][0], s[n][1]);
                *(float2*)&attn[rbase + 8 * (size_t)Sv + col] = make_float2(s[n][2], s[n][3]);
            }
        }

        // ---- online softmax (rows rw+qr and rw+qr+8, quad-reduced) ----
        float mx0 = m0, mx1 = m1;
#pragma unroll
        for (int n = 0; n < 8; n++) {
            mx0 = fmaxf(mx0, fmaxf(s[n][0], s[n][1]));
            mx1 = fmaxf(mx1, fmaxf(s[n][2], s[n][3]));
        }
        mx0 = fmaxf(mx0, __shfl_xor_sync(0xffffffffu, mx0, 1));
        mx0 = fmaxf(mx0, __shfl_xor_sync(0xffffffffu, mx0, 2));
        mx1 = fmaxf(mx1, __shfl_xor_sync(0xffffffffu, mx1, 1));
        mx1 = fmaxf(mx1, __shfl_xor_sync(0xffffffffu, mx1, 2));
        float c0 = __expf(m0 - mx0);
        float c1 = __expf(m1 - mx1);
        m0 = mx0; m1 = mx1;

        float s0 = 0.f, s1 = 0.f;
        const int prow = rw + qr;
#pragma unroll
        for (int n = 0; n < 8; n++) {
            float p00 = __expf(s[n][0] - mx0);
            float p01 = __expf(s[n][1] - mx0);
            float p10 = __expf(s[n][2] - mx1);
            float p11 = __expf(s[n][3] - mx1);
            s0 += p00 + p01;
            s1 += p10 + p11;
            int pcol = n * 8 + 2 * qc;
            Ps[prow * PD + pcol]           = __uint_as_float(f2tf(p00));
            Ps[prow * PD + pcol + 1]       = __uint_as_float(f2tf(p01));
            Ps[(prow + 8) * PD + pcol]     = __uint_as_float(f2tf(p10));
            Ps[(prow + 8) * PD + pcol + 1] = __uint_as_float(f2tf(p11));
        }
        s0 += __shfl_xor_sync(0xffffffffu, s0, 1);
        s0 += __shfl_xor_sync(0xffffffffu, s0, 2);
        s1 += __shfl_xor_sync(0xffffffffu, s1, 1);
        s1 += __shfl_xor_sync(0xffffffffu, s1, 2);
        l0 = l0 * c0 + s0;
        l1 = l1 * c1 + s1;

#pragma unroll
        for (int n = 0; n < 8; n++) {
            o[n][0] *= c0; o[n][1] *= c0;
            o[n][2] *= c1; o[n][3] *= c1;
        }
        __syncwarp();

        // ---- O += P @ V ----
#pragma unroll
        for (int k0 = 0; k0 < 8; k0++) {
            unsigned a[4];
            int arow = rw + qr, acol = k0 * 8 + qc;
            a[0] = __float_as_uint(Ps[arow * PD + acol]);
            a[1] = __float_as_uint(Ps[(arow + 8) * PD + acol]);
            a[2] = __float_as_uint(Ps[arow * PD + acol + 4]);
            a[3] = __float_as_uint(Ps[(arow + 8) * PD + acol + 4]);
#pragma unroll
            for (int n = 0; n < 8; n++) {
                unsigned bf[2];
                bf[0] = __float_as_uint(Vs[(k0 * 8 + qc) * PD + n * 8 + qr]);
                bf[1] = __float_as_uint(Vs[(k0 * 8 + qc + 4) * PD + n * 8 + qr]);
                mma_tf32(o[n], a, bf);
            }
        }
    }

    // epilogue: normalize ctx, write out
    float inv0 = 1.f / l0, inv1 = 1.f / l1;
    size_t crow0 = ((size_t)b * Sv + qt * 64 + rw + qr) * DMv + h * 64;
#pragma unroll
    for (int n = 0; n < 8; n++) {
        int col = n * 8 + 2 * qc;
        *(float2*)&CTX[crow0 + col] =
            make_float2(o[n][0] * inv0, o[n][1] * inv0);
        *(float2*)&CTX[crow0 + 8 * (size_t)DMv + col] =
            make_float2(o[n][2] * inv1, o[n][3] * inv1);
    }
    if (qc == 0) {
        size_t sbase = (size_t)bh * Sv + qt * 64 + rw + qr;
        gm[sbase] = m0;     gl[sbase] = l0;
        gm[sbase + 8] = m1; gl[sbase + 8] = l1;
    }
}

// ---------------- attn normalize: attn = exp(raw - m) / l --------------------
__global__ __launch_bounds__(256) void attn_norm(
    float* __restrict__ attn, const float* __restrict__ gm,
    const float* __restrict__ gl)
{
    size_t i = (size_t)blockIdx.x * blockDim.x + threadIdx.x;   // float4 index
    size_t row = i >> 9;          // 2048 floats = 512 float4 per row
    float m = gm[row];
    float inv = 1.f / gl[row];
    float4 v = ((float4*)attn)[i];
    v.x = __expf(v.x - m) * inv;
    v.y = __expf(v.y - m) * inv;
    v.z = __expf(v.z - m) * inv;
    v.w = __expf(v.w - m) * inv;
    ((float4*)attn)[i] = v;
}

// ---------------- residual add + LayerNorm -----------------------------------
__global__ __launch_bounds__(256) void resid_ln(
    const float* __restrict__ Y, const float* __restrict__ R,
    const float* __restrict__ gamma, const float* __restrict__ beta,
    float* __restrict__ out)
{
    __shared__ float ssum[8], ssq[8], sstat[2];
    const int row = blockIdx.x;
    const int tid = threadIdx.x;
    const int lane = tid & 31, wid = tid >> 5;

    float4 v = *(const float4*)(Y + (size_t)row * DMv + tid * 4);
    float4 r = *(const float4*)(R + (size_t)row * DMv + tid * 4);
    v.x += r.x; v.y += r.y; v.z += r.z; v.w += r.w;

    float s  = v.x + v.y + v.z + v.w;
    float sq = v.x * v.x + v.y * v.y + v.z * v.z + v.w * v.w;
#pragma unroll
    for (int o = 16; o > 0; o >>= 1) {
        s  += __shfl_xor_sync(0xffffffffu, s, o);
        sq += __shfl_xor_sync(0xffffffffu, sq, o);
    }
    if (lane == 0) { ssum[wid] = s; ssq[wid] = sq; }
    __syncthreads();
    if (tid == 0) {
        float ts = 0.f, tq = 0.f;
#pragma unroll
        for (int i = 0; i < 8; i++) { ts += ssum[i]; tq += ssq[i]; }
        float mu = ts * (1.f / DMv);
        float var = tq * (1.f / DMv) - mu * mu;
        sstat[0] = mu;
        sstat[1] = rsqrtf(var + 1e-6f);
    }
    __syncthreads();
    float mu = sstat[0], rstd = sstat[1];

    float4 g = *(const float4*)(gamma + tid * 4);
    float4 be = *(const float4*)(beta + tid * 4);
    float4 o;
    o.x = (v.x - mu) * rstd * g.x + be.x;
    o.y = (v.y - mu) * rstd * g.y + be.y;
    o.z = (v.z - mu) * rstd * g.z + be.z;
    o.w = (v.w - mu) * rstd * g.w + be.w;
    *(float4*)(out + (size_t)row * DMv + tid * 4) = o;
}

// ---------------- launch ------------------------------------------------------
extern "C" void kernel_launch(void* const* d_in, const int* in_sizes, int n_in,
                              void* d_out, int out_size)
{
    const float* q      = (const float*)d_in[0];
    const float* k      = (const float*)d_in[1];
    const float* v      = (const float*)d_in[2];
    const float* w_qs_u = (const float*)d_in[3];
    const float* w_qs_v = (const float*)d_in[4];
    const float* w_ks_u = (const float*)d_in[5];
    const float* w_ks_v = (const float*)d_in[6];
    const float* w_vs_u = (const float*)d_in[7];
    const float* w_vs_v = (const float*)d_in[8];
    const float* fc_u   = (const float*)d_in[9];
    const float* fc_v   = (const float*)d_in[10];
    const float* ln_g   = (const float*)d_in[11];
    const float* ln_b   = (const float*)d_in[12];
    float* out = (float*)d_out;

    float *Tq, *Tk, *Tv, *QHp, *KHp, *VHp, *CTXp, *T4p, *Yp, *mp, *lp;
    cudaGetSymbolAddress((void**)&Tq,  g_Tq);
    cudaGetSymbolAddress((void**)&Tk,  g_Tk);
    cudaGetSymbolAddress((void**)&Tv,  g_Tv);
    cudaGetSymbolAddress((void**)&QHp, g_QH);
    cudaGetSymbolAddress((void**)&KHp, g_KH);
    cudaGetSymbolAddress((void**)&VHp, g_VH);
    cudaGetSymbolAddress((void**)&CTXp, g_CTX);
    cudaGetSymbolAddress((void**)&T4p, g_T4);
    cudaGetSymbolAddress((void**)&Yp,  g_Y);
    cudaGetSymbolAddress((void**)&mp,  g_m);
    cudaGetSymbolAddress((void**)&lp,  g_l);

    const size_t OUTM = (size_t)MR * DMv;                 // 8388608
    const size_t ATTN = (size_t)BHv * Sv * Sv;            // 268435456
    float* attn_ptr = nullptr;
    int wa = 0;
    if ((size_t)out_size >= OUTM + ATTN) { attn_ptr = out + OUTM; wa = 1; }

    cudaFuncSetAttribute(flash_tc,
                         cudaFuncAttributeMaxDynamicSharedMemorySize, FLASH_SMEM);

    dim3 blk(256);
    // low-rank U projections (K=1024 -> N=256), batched into one launch
    sgemm128_b3<<<dim3(RKv / 128, MR / 128, 3), blk>>>(
        q, w_qs_u, Tq,  k, w_ks_u, Tk,  v, w_vs_u, Tv, MR, RKv, DMv);
    // V projections (K=256 -> N=1024), batched
    sgemm128_b3<<<dim3(DMv / 128, MR / 128, 3), blk>>>(
        Tq, w_qs_v, QHp,  Tk, w_ks_v, KHp,  Tv, w_vs_v, VHp, MR, DMv, RKv);
    // attention (tf32 tensor cores)
    flash_tc<<<dim3(Sv / 64, BHv), dim3(128), FLASH_SMEM>>>(
        QHp, KHp, VHp, attn_ptr, CTXp, mp, lp, wa);
    if (wa)
        attn_norm<<<(unsigned)(ATTN / 4 / 256), 256>>>(attn_ptr, mp, lp);
    // FC
    sgemm128_b3<<<dim3(RKv / 128, MR / 128, 1), blk>>>(
        CTXp, fc_u, T4p, CTXp, fc_u, T4p, CTXp, fc_u, T4p, MR, RKv, DMv);
    sgemm128_b3<<<dim3(DMv / 128, MR / 128, 1), blk>>>(
        T4p, fc_v, Yp, T4p, fc_v, Yp, T4p, fc_v, Yp, MR, DMv, RKv);
    // residual + layernorm
    resid_ln<<<MR, blk>>>(Yp, q, ln_g, ln_b, out);
}